// round 1
// baseline (speedup 1.0000x reference)
#include <cuda_runtime.h>
#include <cuda_bf16.h>
#include <math.h>

// ---------------------------------------------------------------------------
// ScaffoldGAN: JTNN GRU message passing + discriminator MLP, fp32 baseline.
//
// Shapes (fixed by setup_inputs):
//   H=450, V=800, N_NODES=4000, N_MESS=6000, K=6, B=256, DH=450, DEPTH=15
//
// Restructure vs reference:
//   * hU = h @ U_r^T computed once per step (6000 rows), then gathered —
//     instead of (h gathered to 36000 rows) @ U_r^T.
//   * x-dependent GEMM halves precomputed once (loop-invariant):
//       xz = x @ Wz[:, :H]^T + b_z
//       xr = x @ W_r^T       + b_Ur      (U_r bias folded here)
//       xh = x @ Wh[:, :H]^T + b_h
//   * Per step: sum_h gather; z = sigmoid(sum_h@Wz[:,H:]^T + xz);
//     hU = h@U_r^T; sum_gh = sum_k sigmoid(xr + hU[g]) * h[g];
//     h  = ((1-z)*sum_h + z*tanh(sum_gh@Wh[:,H:]^T + xh)) * mask
//   * Readout only for B=256 roots; then 2-layer leaky-relu MLP + final dot.
// ---------------------------------------------------------------------------

#define HH   450
#define NNODES 4000
#define NMESS  6000
#define KNB  6
#define BB   256
#define DHH  450
#define MAXDEPTH 15

// ---------------- device scratch (no allocations allowed) ------------------
__device__ float g_fe[NNODES * HH];      // fnode embeddings
__device__ float g_x[NMESS * HH];        // per-message source features
__device__ float g_xz[NMESS * HH];
__device__ float g_xr[NMESS * HH];
__device__ float g_xh[NMESS * HH];
__device__ float g_h[NMESS * HH];        // message hidden state (in-place OK)
__device__ float g_hU[NMESS * HH];
__device__ float g_sumh[NMESS * HH];
__device__ float g_z[NMESS * HH];
__device__ float g_sumgh[NMESS * HH];
__device__ float g_rv[BB * 2 * HH];      // root vectors [B, 2H]
__device__ float g_d1[BB * DHH];
__device__ float g_d2[BB * DHH];

// ---------------------------- small kernels --------------------------------
__global__ void zero_kernel(float* p, int n) {
    int i = blockIdx.x * blockDim.x + threadIdx.x;
    if (i < n) p[i] = 0.f;
}

__global__ void gather_rows_kernel(const float* __restrict__ src,
                                   const int* __restrict__ idx,
                                   float* __restrict__ dst, int rows) {
    int i = blockIdx.x * blockDim.x + threadIdx.x;
    if (i >= rows * HH) return;
    int r = i / HH, c = i - r * HH;
    dst[i] = src[idx[r] * HH + c];
}

__global__ void sum_h_kernel(const float* __restrict__ h,
                             const int* __restrict__ mg,
                             float* __restrict__ out,
                             const int* __restrict__ depthp, int step) {
    if (depthp && step >= __ldg(depthp)) return;
    int i = blockIdx.x * blockDim.x + threadIdx.x;
    if (i >= NMESS * HH) return;
    int m = i / HH, c = i - m * HH;
    float s = 0.f;
#pragma unroll
    for (int k = 0; k < KNB; k++) {
        int j = mg[m * KNB + k];
        s += h[j * HH + c];
    }
    out[i] = s;
}

__global__ void gated_sum_kernel(const float* __restrict__ h,
                                 const float* __restrict__ hU,
                                 const float* __restrict__ xr,
                                 const int* __restrict__ mg,
                                 float* __restrict__ out,
                                 const int* __restrict__ depthp, int step) {
    if (depthp && step >= __ldg(depthp)) return;
    int i = blockIdx.x * blockDim.x + threadIdx.x;
    if (i >= NMESS * HH) return;
    int m = i / HH, c = i - m * HH;
    float xrv = xr[i];
    float s = 0.f;
#pragma unroll
    for (int k = 0; k < KNB; k++) {
        int j = mg[m * KNB + k];
        float hv = h[j * HH + c];
        float r  = 1.f / (1.f + __expf(-(xrv + hU[j * HH + c])));
        s += r * hv;
    }
    out[i] = s;
}

__global__ void readout_kernel(const float* __restrict__ fe,
                               const float* __restrict__ h,
                               const int* __restrict__ root,
                               const int* __restrict__ ng,
                               float* __restrict__ rv) {
    int i = blockIdx.x * blockDim.x + threadIdx.x;
    if (i >= BB * HH) return;
    int b = i / HH, c = i - b * HH;
    int node = root[b];
    rv[b * 2 * HH + c] = fe[node * HH + c];
    float s = 0.f;
#pragma unroll
    for (int k = 0; k < KNB; k++)
        s += h[ng[node * KNB + k] * HH + c];
    rv[b * 2 * HH + HH + c] = s;
}

__global__ void score_kernel(const float* __restrict__ h2,
                             const float* __restrict__ w,
                             const float* __restrict__ b3,
                             float* __restrict__ out) {
    int gt = blockIdx.x * blockDim.x + threadIdx.x;
    int warp = gt >> 5, lane = gt & 31;
    if (warp >= BB) return;
    float s = 0.f;
    for (int k = lane; k < DHH; k += 32) s += h2[warp * DHH + k] * w[k];
#pragma unroll
    for (int o = 16; o; o >>= 1) s += __shfl_xor_sync(0xffffffffu, s, o);
    if (lane == 0) out[warp] = s + b3[0];
}

// ------------------------------ tiled GEMM ---------------------------------
// C[m,n] = epilogue( sum_k A[m*lda+k] * W[n*ldw+k] )
// modes: 0: +bias[n]                     (precompute xz/xr/xh)
//        1: sigmoid(acc + pre[m*N+n])    (z)
//        2: acc                          (hU)
//        3: v = ((1-z)*sumh + z*tanh(acc+pre)) masked at m==0  (h update)
//        4: leaky_relu(acc + bias[n], 0.1)
#define BM 64
#define BN 64
#define BKK 16
#define TM 4
#define TN 4

__global__ __launch_bounds__(256)
void gemm_kernel(const float* __restrict__ A, int lda,
                 const float* __restrict__ W, int ldw,
                 int M, int N, int K, int mode,
                 const float* __restrict__ bias,
                 const float* __restrict__ pre,
                 const float* __restrict__ zbuf,
                 const float* __restrict__ sumh,
                 float* __restrict__ C,
                 const int* __restrict__ depthp, int step) {
    if (depthp && step >= __ldg(depthp)) return;

    __shared__ float As[BKK][BM];
    __shared__ float Ws[BKK][BN];

    int bm = blockIdx.y * BM;
    int bn = blockIdx.x * BN;
    int tid = threadIdx.x;
    int tr = tid >> 4;          // 0..15
    int tc = tid & 15;          // 0..15

    float acc[TM][TN];
#pragma unroll
    for (int i = 0; i < TM; i++)
#pragma unroll
        for (int j = 0; j < TN; j++) acc[i][j] = 0.f;

    for (int k0 = 0; k0 < K; k0 += BKK) {
#pragma unroll
        for (int t = 0; t < 4; t++) {
            int l = tid + t * 256;
            int i = l >> 4, j = l & 15;
            int gm = bm + i, gk = k0 + j;
            As[j][i] = (gm < M && gk < K) ? A[gm * lda + gk] : 0.f;
        }
#pragma unroll
        for (int t = 0; t < 4; t++) {
            int l = tid + t * 256;
            int i = l >> 4, j = l & 15;
            int gn = bn + i, gk = k0 + j;
            Ws[j][i] = (gn < N && gk < K) ? W[gn * ldw + gk] : 0.f;
        }
        __syncthreads();
#pragma unroll
        for (int kk = 0; kk < BKK; kk++) {
            float a[TM], w[TN];
#pragma unroll
            for (int i = 0; i < TM; i++) a[i] = As[kk][tr * TM + i];
#pragma unroll
            for (int j = 0; j < TN; j++) w[j] = Ws[kk][tc * TN + j];
#pragma unroll
            for (int i = 0; i < TM; i++)
#pragma unroll
                for (int j = 0; j < TN; j++) acc[i][j] += a[i] * w[j];
        }
        __syncthreads();
    }

#pragma unroll
    for (int i = 0; i < TM; i++) {
        int m = bm + tr * TM + i;
        if (m >= M) continue;
#pragma unroll
        for (int j = 0; j < TN; j++) {
            int n = bn + tc * TN + j;
            if (n >= N) continue;
            float v = acc[i][j];
            int idx = m * N + n;
            if (mode == 0) {
                v += bias[n];
            } else if (mode == 1) {
                v = 1.f / (1.f + __expf(-(v + pre[idx])));
            } else if (mode == 3) {
                float ph = tanhf(v + pre[idx]);
                float zv = zbuf[idx];
                v = (1.f - zv) * sumh[idx] + zv * ph;
                if (m == 0) v = 0.f;
            } else if (mode == 4) {
                v += bias[n];
                v = (v > 0.f) ? v : 0.1f * v;
            }
            C[idx] = v;   // ldc == N everywhere here
        }
    }
}

// ------------------------------- launcher ----------------------------------
static inline dim3 gemm_grid(int M, int N) {
    return dim3((N + BN - 1) / BN, (M + BM - 1) / BM);
}

extern "C" void kernel_launch(void* const* d_in, const int* in_sizes, int n_in,
                              void* d_out, int out_size) {
    const int*   fnode      = (const int*)d_in[0];
    const int*   fmess      = (const int*)d_in[1];
    const int*   node_graph = (const int*)d_in[2];
    const int*   mess_graph = (const int*)d_in[3];
    const int*   root_idx   = (const int*)d_in[4];
    const float* emb        = (const float*)d_in[5];
    const float* W_z_w      = (const float*)d_in[6];
    const float* W_z_b      = (const float*)d_in[7];
    const float* W_r_w      = (const float*)d_in[8];
    const float* U_r_w      = (const float*)d_in[9];
    const float* U_r_b      = (const float*)d_in[10];
    const float* W_h_w      = (const float*)d_in[11];
    const float* W_h_b      = (const float*)d_in[12];
    const float* D1_w       = (const float*)d_in[13];
    const float* D1_b       = (const float*)d_in[14];
    const float* D2_w       = (const float*)d_in[15];
    const float* D2_b       = (const float*)d_in[16];
    const float* D3_w       = (const float*)d_in[17];
    const float* D3_b       = (const float*)d_in[18];
    const int*   depthp     = (n_in > 19) ? (const int*)d_in[19] : nullptr;
    float*       out        = (float*)d_out;

    float *fe, *x, *xz, *xr, *xh, *h, *hU, *sumh, *z, *sumgh, *rv, *d1, *d2;
    cudaGetSymbolAddress((void**)&fe,    g_fe);
    cudaGetSymbolAddress((void**)&x,     g_x);
    cudaGetSymbolAddress((void**)&xz,    g_xz);
    cudaGetSymbolAddress((void**)&xr,    g_xr);
    cudaGetSymbolAddress((void**)&xh,    g_xh);
    cudaGetSymbolAddress((void**)&h,     g_h);
    cudaGetSymbolAddress((void**)&hU,    g_hU);
    cudaGetSymbolAddress((void**)&sumh,  g_sumh);
    cudaGetSymbolAddress((void**)&z,     g_z);
    cudaGetSymbolAddress((void**)&sumgh, g_sumgh);
    cudaGetSymbolAddress((void**)&rv,    g_rv);
    cudaGetSymbolAddress((void**)&d1,    g_d1);
    cudaGetSymbolAddress((void**)&d2,    g_d2);

    const int TPB = 256;
    const int MH  = NMESS * HH;

    // h0 = 0 (must re-run every call for determinism)
    zero_kernel<<<(MH + TPB - 1) / TPB, TPB>>>(h, MH);

    // embeddings + per-message source features
    gather_rows_kernel<<<(NNODES * HH + TPB - 1) / TPB, TPB>>>(emb, fnode, fe, NNODES);
    gather_rows_kernel<<<(MH + TPB - 1) / TPB, TPB>>>(fe, fmess, x, NMESS);

    // loop-invariant GEMMs
    gemm_kernel<<<gemm_grid(NMESS, HH), 256>>>(x, HH, W_z_w, 2 * HH, NMESS, HH, HH,
                                               0, W_z_b, nullptr, nullptr, nullptr, xz, nullptr, 0);
    gemm_kernel<<<gemm_grid(NMESS, HH), 256>>>(x, HH, W_h_w, 2 * HH, NMESS, HH, HH,
                                               0, W_h_b, nullptr, nullptr, nullptr, xh, nullptr, 0);
    gemm_kernel<<<gemm_grid(NMESS, HH), 256>>>(x, HH, W_r_w, HH, NMESS, HH, HH,
                                               0, U_r_b, nullptr, nullptr, nullptr, xr, nullptr, 0);

    // GRU steps (device-side depth guard; fixed launch count for graph capture)
    for (int step = 0; step < MAXDEPTH; step++) {
        sum_h_kernel<<<(MH + TPB - 1) / TPB, TPB>>>(h, mess_graph, sumh, depthp, step);
        gemm_kernel<<<gemm_grid(NMESS, HH), 256>>>(sumh, HH, W_z_w + HH, 2 * HH,
                                                   NMESS, HH, HH, 1, nullptr, xz,
                                                   nullptr, nullptr, z, depthp, step);
        gemm_kernel<<<gemm_grid(NMESS, HH), 256>>>(h, HH, U_r_w, HH,
                                                   NMESS, HH, HH, 2, nullptr, nullptr,
                                                   nullptr, nullptr, hU, depthp, step);
        gated_sum_kernel<<<(MH + TPB - 1) / TPB, TPB>>>(h, hU, xr, mess_graph, sumgh,
                                                        depthp, step);
        gemm_kernel<<<gemm_grid(NMESS, HH), 256>>>(sumgh, HH, W_h_w + HH, 2 * HH,
                                                   NMESS, HH, HH, 3, nullptr, xh,
                                                   z, sumh, h, depthp, step);
    }

    // root readout + discriminator
    readout_kernel<<<(BB * HH + TPB - 1) / TPB, TPB>>>(fe, h, root_idx, node_graph, rv);
    gemm_kernel<<<gemm_grid(BB, DHH), 256>>>(rv, 2 * HH, D1_w, 2 * HH, BB, DHH, 2 * HH,
                                             4, D1_b, nullptr, nullptr, nullptr, d1, nullptr, 0);
    gemm_kernel<<<gemm_grid(BB, DHH), 256>>>(d1, DHH, D2_w, DHH, BB, DHH, DHH,
                                             4, D2_b, nullptr, nullptr, nullptr, d2, nullptr, 0);
    score_kernel<<<(BB * 32 + TPB - 1) / TPB, TPB>>>(d2, D3_w, D3_b, out);
}

// round 2
// speedup vs baseline: 1.6992x; 1.6992x over previous
#include <cuda_runtime.h>
#include <cuda_bf16.h>
#include <math.h>

// ---------------------------------------------------------------------------
// ScaffoldGAN: JTNN GRU message passing + discriminator MLP, fp32.
// R2: GEMM upgraded to 128x64x16 block tile, 8x4 register tile, float2 global
//     loads, float4 smem reads. Targets FMA roofline instead of L1 roofline.
// ---------------------------------------------------------------------------

#define HH   450
#define NNODES 4000
#define NMESS  6000
#define KNB  6
#define BB   256
#define DHH  450
#define MAXDEPTH 15

// ---------------- device scratch (no allocations allowed) ------------------
__device__ float g_fe[NNODES * HH];
__device__ float g_x[NMESS * HH];
__device__ float g_xz[NMESS * HH];
__device__ float g_xr[NMESS * HH];
__device__ float g_xh[NMESS * HH];
__device__ float g_h[NMESS * HH];
__device__ float g_hU[NMESS * HH];
__device__ float g_sumh[NMESS * HH];
__device__ float g_z[NMESS * HH];
__device__ float g_sumgh[NMESS * HH];
__device__ float g_rv[BB * 2 * HH];
__device__ float g_d1[BB * DHH];
__device__ float g_d2[BB * DHH];

// ---------------------------- small kernels --------------------------------
__global__ void zero_kernel(float* p, int n) {
    int i = blockIdx.x * blockDim.x + threadIdx.x;
    if (i < n) p[i] = 0.f;
}

__global__ void gather_rows_kernel(const float* __restrict__ src,
                                   const int* __restrict__ idx,
                                   float* __restrict__ dst, int rows) {
    int i = blockIdx.x * blockDim.x + threadIdx.x;
    if (i >= rows * HH) return;
    int r = i / HH, c = i - r * HH;
    dst[i] = src[idx[r] * HH + c];
}

__global__ void sum_h_kernel(const float* __restrict__ h,
                             const int* __restrict__ mg,
                             float* __restrict__ out,
                             const int* __restrict__ depthp, int step) {
    if (depthp && step >= __ldg(depthp)) return;
    int i = blockIdx.x * blockDim.x + threadIdx.x;
    if (i >= NMESS * HH) return;
    int m = i / HH, c = i - m * HH;
    float s = 0.f;
#pragma unroll
    for (int k = 0; k < KNB; k++) {
        int j = mg[m * KNB + k];
        s += h[j * HH + c];
    }
    out[i] = s;
}

__global__ void gated_sum_kernel(const float* __restrict__ h,
                                 const float* __restrict__ hU,
                                 const float* __restrict__ xr,
                                 const int* __restrict__ mg,
                                 float* __restrict__ out,
                                 const int* __restrict__ depthp, int step) {
    if (depthp && step >= __ldg(depthp)) return;
    int i = blockIdx.x * blockDim.x + threadIdx.x;
    if (i >= NMESS * HH) return;
    int m = i / HH, c = i - m * HH;
    float xrv = xr[i];
    float s = 0.f;
#pragma unroll
    for (int k = 0; k < KNB; k++) {
        int j = mg[m * KNB + k];
        float hv = h[j * HH + c];
        float r  = 1.f / (1.f + __expf(-(xrv + hU[j * HH + c])));
        s += r * hv;
    }
    out[i] = s;
}

__global__ void readout_kernel(const float* __restrict__ fe,
                               const float* __restrict__ h,
                               const int* __restrict__ root,
                               const int* __restrict__ ng,
                               float* __restrict__ rv) {
    int i = blockIdx.x * blockDim.x + threadIdx.x;
    if (i >= BB * HH) return;
    int b = i / HH, c = i - b * HH;
    int node = root[b];
    rv[b * 2 * HH + c] = fe[node * HH + c];
    float s = 0.f;
#pragma unroll
    for (int k = 0; k < KNB; k++)
        s += h[ng[node * KNB + k] * HH + c];
    rv[b * 2 * HH + HH + c] = s;
}

__global__ void score_kernel(const float* __restrict__ h2,
                             const float* __restrict__ w,
                             const float* __restrict__ b3,
                             float* __restrict__ out) {
    int gt = blockIdx.x * blockDim.x + threadIdx.x;
    int warp = gt >> 5, lane = gt & 31;
    if (warp >= BB) return;
    float s = 0.f;
    for (int k = lane; k < DHH; k += 32) s += h2[warp * DHH + k] * w[k];
#pragma unroll
    for (int o = 16; o; o >>= 1) s += __shfl_xor_sync(0xffffffffu, s, o);
    if (lane == 0) out[warp] = s + b3[0];
}

// ------------------------------ tiled GEMM ---------------------------------
// C[m,n] = epilogue( sum_k A[m*lda+k] * W[n*ldw+k] )
// modes: 0: +bias[n]
//        1: sigmoid(acc + pre[m*N+n])
//        2: acc
//        3: ((1-z)*sumh + z*tanh(acc+pre)) masked at m==0
//        4: leaky_relu(acc + bias[n], 0.1)
#define BM 128
#define BN 64
#define BKK 16
#define TM 8
#define TN 4
#define ASTRIDE (BM + 4)   // 132, multiple of 4 for float4 LDS
#define WSTRIDE (BN + 4)   // 68,  multiple of 4 for float4 LDS

__global__ __launch_bounds__(256)
void gemm_kernel(const float* __restrict__ A, int lda,
                 const float* __restrict__ W, int ldw,
                 int M, int N, int K, int mode,
                 const float* __restrict__ bias,
                 const float* __restrict__ pre,
                 const float* __restrict__ zbuf,
                 const float* __restrict__ sumh,
                 float* __restrict__ C,
                 const int* __restrict__ depthp, int step) {
    if (depthp && step >= __ldg(depthp)) return;

    __shared__ float As[BKK][ASTRIDE];
    __shared__ float Ws[BKK][WSTRIDE];

    const int bm = blockIdx.y * BM;
    const int bn = blockIdx.x * BN;
    const int tid = threadIdx.x;
    const int tr = tid >> 4;   // 0..15 -> 8 rows each
    const int tc = tid & 15;   // 0..15 -> 4 cols each

    float acc[TM][TN];
#pragma unroll
    for (int i = 0; i < TM; i++)
#pragma unroll
        for (int j = 0; j < TN; j++) acc[i][j] = 0.f;

    for (int k0 = 0; k0 < K; k0 += BKK) {
        // Load A tile: 128 rows x 16 k = 1024 float2 slots, 4 per thread.
#pragma unroll
        for (int t = 0; t < 4; t++) {
            int l  = tid + t * 256;
            int r  = l >> 3;           // 0..127
            int kp = (l & 7) << 1;     // 0,2,...,14
            int gm = bm + r, gk = k0 + kp;
            float vx = 0.f, vy = 0.f;
            if (gm < M) {
                if (gk + 1 < K) {
                    float2 v = *reinterpret_cast<const float2*>(&A[gm * lda + gk]);
                    vx = v.x; vy = v.y;
                } else if (gk < K) {
                    vx = A[gm * lda + gk];
                }
            }
            As[kp][r]     = vx;
            As[kp + 1][r] = vy;
        }
        // Load W tile: 64 rows x 16 k = 512 float2 slots, 2 per thread.
#pragma unroll
        for (int t = 0; t < 2; t++) {
            int l  = tid + t * 256;
            int r  = l >> 3;           // 0..63
            int kp = (l & 7) << 1;
            int gn = bn + r, gk = k0 + kp;
            float vx = 0.f, vy = 0.f;
            if (gn < N) {
                if (gk + 1 < K) {
                    float2 v = *reinterpret_cast<const float2*>(&W[gn * ldw + gk]);
                    vx = v.x; vy = v.y;
                } else if (gk < K) {
                    vx = W[gn * ldw + gk];
                }
            }
            Ws[kp][r]     = vx;
            Ws[kp + 1][r] = vy;
        }
        __syncthreads();

#pragma unroll
        for (int kk = 0; kk < BKK; kk++) {
            const float4* a4 = reinterpret_cast<const float4*>(&As[kk][tr * TM]);
            float4 a0 = a4[0];
            float4 a1 = a4[1];
            float4 w0 = *reinterpret_cast<const float4*>(&Ws[kk][tc * TN]);
            float a[TM] = {a0.x, a0.y, a0.z, a0.w, a1.x, a1.y, a1.z, a1.w};
            float w[TN] = {w0.x, w0.y, w0.z, w0.w};
#pragma unroll
            for (int i = 0; i < TM; i++)
#pragma unroll
                for (int j = 0; j < TN; j++) acc[i][j] += a[i] * w[j];
        }
        __syncthreads();
    }

#pragma unroll
    for (int i = 0; i < TM; i++) {
        int m = bm + tr * TM + i;
        if (m >= M) continue;
#pragma unroll
        for (int j = 0; j < TN; j++) {
            int n = bn + tc * TN + j;
            if (n >= N) continue;
            float v = acc[i][j];
            int idx = m * N + n;
            if (mode == 0) {
                v += bias[n];
            } else if (mode == 1) {
                v = 1.f / (1.f + __expf(-(v + pre[idx])));
            } else if (mode == 3) {
                float ph = tanhf(v + pre[idx]);
                float zv = zbuf[idx];
                v = (1.f - zv) * sumh[idx] + zv * ph;
                if (m == 0) v = 0.f;
            } else if (mode == 4) {
                v += bias[n];
                v = (v > 0.f) ? v : 0.1f * v;
            }
            C[idx] = v;
        }
    }
}

// ------------------------------- launcher ----------------------------------
static inline dim3 gemm_grid(int M, int N) {
    return dim3((N + BN - 1) / BN, (M + BM - 1) / BM);
}

extern "C" void kernel_launch(void* const* d_in, const int* in_sizes, int n_in,
                              void* d_out, int out_size) {
    const int*   fnode      = (const int*)d_in[0];
    const int*   fmess      = (const int*)d_in[1];
    const int*   node_graph = (const int*)d_in[2];
    const int*   mess_graph = (const int*)d_in[3];
    const int*   root_idx   = (const int*)d_in[4];
    const float* emb        = (const float*)d_in[5];
    const float* W_z_w      = (const float*)d_in[6];
    const float* W_z_b      = (const float*)d_in[7];
    const float* W_r_w      = (const float*)d_in[8];
    const float* U_r_w      = (const float*)d_in[9];
    const float* U_r_b      = (const float*)d_in[10];
    const float* W_h_w      = (const float*)d_in[11];
    const float* W_h_b      = (const float*)d_in[12];
    const float* D1_w       = (const float*)d_in[13];
    const float* D1_b       = (const float*)d_in[14];
    const float* D2_w       = (const float*)d_in[15];
    const float* D2_b       = (const float*)d_in[16];
    const float* D3_w       = (const float*)d_in[17];
    const float* D3_b       = (const float*)d_in[18];
    const int*   depthp     = (n_in > 19) ? (const int*)d_in[19] : nullptr;
    float*       out        = (float*)d_out;

    float *fe, *x, *xz, *xr, *xh, *h, *hU, *sumh, *z, *sumgh, *rv, *d1, *d2;
    cudaGetSymbolAddress((void**)&fe,    g_fe);
    cudaGetSymbolAddress((void**)&x,     g_x);
    cudaGetSymbolAddress((void**)&xz,    g_xz);
    cudaGetSymbolAddress((void**)&xr,    g_xr);
    cudaGetSymbolAddress((void**)&xh,    g_xh);
    cudaGetSymbolAddress((void**)&h,     g_h);
    cudaGetSymbolAddress((void**)&hU,    g_hU);
    cudaGetSymbolAddress((void**)&sumh,  g_sumh);
    cudaGetSymbolAddress((void**)&z,     g_z);
    cudaGetSymbolAddress((void**)&sumgh, g_sumgh);
    cudaGetSymbolAddress((void**)&rv,    g_rv);
    cudaGetSymbolAddress((void**)&d1,    g_d1);
    cudaGetSymbolAddress((void**)&d2,    g_d2);

    const int TPB = 256;
    const int MH  = NMESS * HH;

    zero_kernel<<<(MH + TPB - 1) / TPB, TPB>>>(h, MH);

    gather_rows_kernel<<<(NNODES * HH + TPB - 1) / TPB, TPB>>>(emb, fnode, fe, NNODES);
    gather_rows_kernel<<<(MH + TPB - 1) / TPB, TPB>>>(fe, fmess, x, NMESS);

    gemm_kernel<<<gemm_grid(NMESS, HH), 256>>>(x, HH, W_z_w, 2 * HH, NMESS, HH, HH,
                                               0, W_z_b, nullptr, nullptr, nullptr, xz, nullptr, 0);
    gemm_kernel<<<gemm_grid(NMESS, HH), 256>>>(x, HH, W_h_w, 2 * HH, NMESS, HH, HH,
                                               0, W_h_b, nullptr, nullptr, nullptr, xh, nullptr, 0);
    gemm_kernel<<<gemm_grid(NMESS, HH), 256>>>(x, HH, W_r_w, HH, NMESS, HH, HH,
                                               0, U_r_b, nullptr, nullptr, nullptr, xr, nullptr, 0);

    for (int step = 0; step < MAXDEPTH; step++) {
        sum_h_kernel<<<(MH + TPB - 1) / TPB, TPB>>>(h, mess_graph, sumh, depthp, step);
        gemm_kernel<<<gemm_grid(NMESS, HH), 256>>>(sumh, HH, W_z_w + HH, 2 * HH,
                                                   NMESS, HH, HH, 1, nullptr, xz,
                                                   nullptr, nullptr, z, depthp, step);
        gemm_kernel<<<gemm_grid(NMESS, HH), 256>>>(h, HH, U_r_w, HH,
                                                   NMESS, HH, HH, 2, nullptr, nullptr,
                                                   nullptr, nullptr, hU, depthp, step);
        gated_sum_kernel<<<(MH + TPB - 1) / TPB, TPB>>>(h, hU, xr, mess_graph, sumgh,
                                                        depthp, step);
        gemm_kernel<<<gemm_grid(NMESS, HH), 256>>>(sumgh, HH, W_h_w + HH, 2 * HH,
                                                   NMESS, HH, HH, 3, nullptr, xh,
                                                   z, sumh, h, depthp, step);
    }

    readout_kernel<<<(BB * HH + TPB - 1) / TPB, TPB>>>(fe, h, root_idx, node_graph, rv);
    gemm_kernel<<<gemm_grid(BB, DHH), 256>>>(rv, 2 * HH, D1_w, 2 * HH, BB, DHH, 2 * HH,
                                             4, D1_b, nullptr, nullptr, nullptr, d1, nullptr, 0);
    gemm_kernel<<<gemm_grid(BB, DHH), 256>>>(d1, DHH, D2_w, DHH, BB, DHH, DHH,
                                             4, D2_b, nullptr, nullptr, nullptr, d2, nullptr, 0);
    score_kernel<<<(BB * 32 + TPB - 1) / TPB, TPB>>>(d2, D3_w, D3_b, out);
}

// round 3
// speedup vs baseline: 1.7732x; 1.0435x over previous
#include <cuda_runtime.h>
#include <cuda_bf16.h>
#include <math.h>

// ---------------------------------------------------------------------------
// ScaffoldGAN JTNN GRU + discriminator, fp32. R3:
//  * 128x128x16 double-buffered SIMT GEMM, 8x8 register tile.
//  * Per step: ONE fused N=900 GEMM (h@[Wz_h;U_r]) + fused gather (sum_h, z,
//    sum_gh in one pass, using linearity of sum over neighbors) + N=450 GEMM.
//  * Precompute xz/xh/xr as ONE N=1350 GEMM with pre-packed weights.
//  * Step 0 specialized (h0 = 0 -> pure elementwise).
// ---------------------------------------------------------------------------

#define HH     450
#define NNODES 4000
#define NMESS  6000
#define KNB    6
#define BB     256
#define DHH    450
#define MAXDEPTH 15

// ---------------- device scratch ------------------
__device__ float g_fe[NNODES * HH];
__device__ float g_x[NMESS * HH];
__device__ float g_xzrh[NMESS * 3 * HH];   // [M][1350]: xz | xh | xr
__device__ float g_h[NMESS * HH];
__device__ float g_hZU[NMESS * 2 * HH];    // [M][900]: h@Wz_h | h@U_r
__device__ float g_sumh[NMESS * HH];
__device__ float g_z[NMESS * HH];
__device__ float g_sumgh[NMESS * HH];
__device__ float g_Wpre[3 * HH * HH];      // [1350][450]
__device__ float g_bpre[3 * HH];
__device__ float g_Wstep[2 * HH * HH];     // [900][450]
__device__ float g_rv[BB * 2 * HH];
__device__ float g_d1[BB * DHH];
__device__ float g_d2[BB * DHH];

// ---------------------------- small kernels --------------------------------
__global__ void zero_kernel(float* p, int n) {
    int i = blockIdx.x * blockDim.x + threadIdx.x;
    if (i < n) p[i] = 0.f;
}

__global__ void pack_kernel(const float* __restrict__ W_z_w,
                            const float* __restrict__ W_h_w,
                            const float* __restrict__ W_r_w,
                            const float* __restrict__ U_r_w,
                            const float* __restrict__ W_z_b,
                            const float* __restrict__ W_h_b,
                            const float* __restrict__ U_r_b,
                            float* __restrict__ Wpre,
                            float* __restrict__ bpre,
                            float* __restrict__ Wstep) {
    int i = blockIdx.x * blockDim.x + threadIdx.x;
    const int NPRE = 3 * HH * HH;
    const int NSTEP = 2 * HH * HH;
    if (i < NPRE) {
        int n = i / HH, k = i - n * HH;
        float v;
        if (n < HH)            v = W_z_w[n * 2 * HH + k];
        else if (n < 2 * HH)   v = W_h_w[(n - HH) * 2 * HH + k];
        else                   v = W_r_w[(n - 2 * HH) * HH + k];
        Wpre[i] = v;
        if (i < 3 * HH) {
            int n2 = i;
            bpre[n2] = (n2 < HH) ? W_z_b[n2]
                     : (n2 < 2 * HH) ? W_h_b[n2 - HH]
                     : U_r_b[n2 - 2 * HH];
        }
    } else if (i < NPRE + NSTEP) {
        int j = i - NPRE;
        int n = j / HH, k = j - n * HH;
        Wstep[j] = (n < HH) ? W_z_w[n * 2 * HH + HH + k]
                            : U_r_w[(n - HH) * HH + k];
    }
}

__global__ void gather_rows_kernel(const float* __restrict__ src,
                                   const int* __restrict__ idx,
                                   float* __restrict__ dst, int rows) {
    int i = blockIdx.x * blockDim.x + threadIdx.x;
    if (i >= rows * HH) return;
    int r = i / HH, c = i - r * HH;
    dst[i] = src[idx[r] * HH + c];
}

// step 0: h = mask * sigmoid(xz) * tanh(xh)
__global__ void step0_kernel(const float* __restrict__ xzrh,
                             float* __restrict__ h,
                             const int* __restrict__ depthp) {
    if (depthp && __ldg(depthp) < 1) return;
    int i = blockIdx.x * blockDim.x + threadIdx.x;
    if (i >= NMESS * HH) return;
    int m = i / HH, c = i - m * HH;
    float xzv = xzrh[m * 3 * HH + c];
    float xhv = xzrh[m * 3 * HH + HH + c];
    float zv = 1.f / (1.f + __expf(-xzv));
    float v = zv * tanhf(xhv);
    h[i] = (m == 0) ? 0.f : v;
}

// Fused gather: sum_h, z = sigmoid(gsum(hWz)+xz), sum_gh
__global__ void step_gather_kernel(const float* __restrict__ h,
                                   const float* __restrict__ hZU,
                                   const float* __restrict__ xzrh,
                                   const int* __restrict__ mg,
                                   float* __restrict__ sumh,
                                   float* __restrict__ z,
                                   float* __restrict__ sumgh,
                                   const int* __restrict__ depthp, int step) {
    if (depthp && step >= __ldg(depthp)) return;
    int i = blockIdx.x * blockDim.x + threadIdx.x;
    if (i >= NMESS * HH) return;
    int m = i / HH, c = i - m * HH;
    float xrv = xzrh[m * 3 * HH + 2 * HH + c];
    float sh = 0.f, sz = 0.f, sg = 0.f;
#pragma unroll
    for (int k = 0; k < KNB; k++) {
        int j = mg[m * KNB + k];
        float hv = h[j * HH + c];
        sh += hv;
        sz += hZU[j * 2 * HH + c];
        float u = hZU[j * 2 * HH + HH + c];
        sg += hv / (1.f + __expf(-(xrv + u)));
    }
    sumh[i] = sh;
    float xzv = xzrh[m * 3 * HH + c];
    z[i] = 1.f / (1.f + __expf(-(sz + xzv)));
    sumgh[i] = sg;
}

__global__ void readout_kernel(const float* __restrict__ fe,
                               const float* __restrict__ h,
                               const int* __restrict__ root,
                               const int* __restrict__ ng,
                               float* __restrict__ rv) {
    int i = blockIdx.x * blockDim.x + threadIdx.x;
    if (i >= BB * HH) return;
    int b = i / HH, c = i - b * HH;
    int node = root[b];
    rv[b * 2 * HH + c] = fe[node * HH + c];
    float s = 0.f;
#pragma unroll
    for (int k = 0; k < KNB; k++)
        s += h[ng[node * KNB + k] * HH + c];
    rv[b * 2 * HH + HH + c] = s;
}

__global__ void score_kernel(const float* __restrict__ h2,
                             const float* __restrict__ w,
                             const float* __restrict__ b3,
                             float* __restrict__ out) {
    int gt = blockIdx.x * blockDim.x + threadIdx.x;
    int warp = gt >> 5, lane = gt & 31;
    if (warp >= BB) return;
    float s = 0.f;
    for (int k = lane; k < DHH; k += 32) s += h2[warp * DHH + k] * w[k];
#pragma unroll
    for (int o = 16; o; o >>= 1) s += __shfl_xor_sync(0xffffffffu, s, o);
    if (lane == 0) out[warp] = s + b3[0];
}

// ------------------------------ tiled GEMM ---------------------------------
// C[m*ldc+n] = epilogue( sum_k A[m*lda+k] * W[n*ldw+k] )
// modes: 0: +bias[n]
//        2: plain
//        3: ((1-z)*sumh + z*tanh(acc + pre[m*ldpre+n])), zero row m==0
//        4: leaky_relu(acc + bias[n], 0.1)
#define BM 128
#define BN 128
#define BK 16
#define TM 8
#define TN 8
#define ASTR (BM + 4)
#define WSTR (BN + 4)

__global__ __launch_bounds__(256, 2)
void gemm_kernel(const float* __restrict__ A, int lda,
                 const float* __restrict__ W, int ldw,
                 int M, int N, int K, int mode,
                 const float* __restrict__ bias,
                 const float* __restrict__ pre, int ldpre,
                 const float* __restrict__ zbuf,
                 const float* __restrict__ sumh,
                 float* __restrict__ C, int ldc,
                 const int* __restrict__ depthp, int step) {
    if (depthp && step >= __ldg(depthp)) return;

    __shared__ float As[2][BK][ASTR];
    __shared__ float Ws[2][BK][WSTR];

    const int bm = blockIdx.y * BM;
    const int bn = blockIdx.x * BN;
    const int tid = threadIdx.x;
    const int tr = tid >> 4;   // 0..15
    const int tc = tid & 15;   // 0..15

    float acc[TM][TN];
#pragma unroll
    for (int i = 0; i < TM; i++)
#pragma unroll
        for (int j = 0; j < TN; j++) acc[i][j] = 0.f;

    const int NT = (K + BK - 1) / BK;

    // per-thread load coords: 4 float2 for A, 4 float2 for W
    int lr[4], lkp[4];
#pragma unroll
    for (int t = 0; t < 4; t++) {
        int l = tid + t * 256;
        lr[t] = l >> 3;
        lkp[t] = (l & 7) << 1;
    }

    // prologue: load tile 0 into buf 0
#pragma unroll
    for (int t = 0; t < 4; t++) {
        int gm = bm + lr[t], gk = lkp[t];
        float vx = 0.f, vy = 0.f;
        if (gm < M && gk + 1 < K) {
            float2 v = *reinterpret_cast<const float2*>(&A[gm * lda + gk]);
            vx = v.x; vy = v.y;
        } else if (gm < M && gk < K) vx = A[gm * lda + gk];
        As[0][lkp[t]][lr[t]] = vx;
        As[0][lkp[t] + 1][lr[t]] = vy;
        int gn = bn + lr[t];
        float wx = 0.f, wy = 0.f;
        if (gn < N && gk + 1 < K) {
            float2 v = *reinterpret_cast<const float2*>(&W[gn * ldw + gk]);
            wx = v.x; wy = v.y;
        } else if (gn < N && gk < K) wx = W[gn * ldw + gk];
        Ws[0][lkp[t]][lr[t]] = wx;
        Ws[0][lkp[t] + 1][lr[t]] = wy;
    }
    __syncthreads();

    for (int t0 = 0; t0 < NT; t0++) {
        const int cur = t0 & 1, nxt = cur ^ 1;
        float2 ra[4], rw[4];
        const bool more = (t0 + 1 < NT);
        if (more) {
            int k0 = (t0 + 1) * BK;
#pragma unroll
            for (int t = 0; t < 4; t++) {
                int gm = bm + lr[t], gk = k0 + lkp[t];
                float2 v = make_float2(0.f, 0.f);
                if (gm < M && gk + 1 < K)
                    v = *reinterpret_cast<const float2*>(&A[gm * lda + gk]);
                else if (gm < M && gk < K) v.x = A[gm * lda + gk];
                ra[t] = v;
                int gn = bn + lr[t];
                float2 w = make_float2(0.f, 0.f);
                if (gn < N && gk + 1 < K)
                    w = *reinterpret_cast<const float2*>(&W[gn * ldw + gk]);
                else if (gn < N && gk < K) w.x = W[gn * ldw + gk];
                rw[t] = w;
            }
        }
#pragma unroll
        for (int kk = 0; kk < BK; kk++) {
            float4 a0 = *reinterpret_cast<const float4*>(&As[cur][kk][tr * TM]);
            float4 a1 = *reinterpret_cast<const float4*>(&As[cur][kk][tr * TM + 4]);
            float4 w0 = *reinterpret_cast<const float4*>(&Ws[cur][kk][tc * TN]);
            float4 w1 = *reinterpret_cast<const float4*>(&Ws[cur][kk][tc * TN + 4]);
            float a[TM] = {a0.x, a0.y, a0.z, a0.w, a1.x, a1.y, a1.z, a1.w};
            float w[TN] = {w0.x, w0.y, w0.z, w0.w, w1.x, w1.y, w1.z, w1.w};
#pragma unroll
            for (int i = 0; i < TM; i++)
#pragma unroll
                for (int j = 0; j < TN; j++) acc[i][j] += a[i] * w[j];
        }
        if (more) {
#pragma unroll
            for (int t = 0; t < 4; t++) {
                As[nxt][lkp[t]][lr[t]]     = ra[t].x;
                As[nxt][lkp[t] + 1][lr[t]] = ra[t].y;
                Ws[nxt][lkp[t]][lr[t]]     = rw[t].x;
                Ws[nxt][lkp[t] + 1][lr[t]] = rw[t].y;
            }
        }
        __syncthreads();
    }

#pragma unroll
    for (int i = 0; i < TM; i++) {
        int m = bm + tr * TM + i;
        if (m >= M) continue;
#pragma unroll
        for (int j = 0; j < TN; j++) {
            int n = bn + tc * TN + j;
            if (n >= N) continue;
            float v = acc[i][j];
            if (mode == 0) {
                v += bias[n];
            } else if (mode == 3) {
                float ph = tanhf(v + pre[m * ldpre + n]);
                float zv = zbuf[m * HH + n];
                v = (1.f - zv) * sumh[m * HH + n] + zv * ph;
                if (m == 0) v = 0.f;
            } else if (mode == 4) {
                v += bias[n];
                v = (v > 0.f) ? v : 0.1f * v;
            }
            C[m * ldc + n] = v;
        }
    }
}

// ------------------------------- launcher ----------------------------------
static inline dim3 gemm_grid(int M, int N) {
    return dim3((N + BN - 1) / BN, (M + BM - 1) / BM);
}

extern "C" void kernel_launch(void* const* d_in, const int* in_sizes, int n_in,
                              void* d_out, int out_size) {
    const int*   fnode      = (const int*)d_in[0];
    const int*   fmess      = (const int*)d_in[1];
    const int*   node_graph = (const int*)d_in[2];
    const int*   mess_graph = (const int*)d_in[3];
    const int*   root_idx   = (const int*)d_in[4];
    const float* emb        = (const float*)d_in[5];
    const float* W_z_w      = (const float*)d_in[6];
    const float* W_z_b      = (const float*)d_in[7];
    const float* W_r_w      = (const float*)d_in[8];
    const float* U_r_w      = (const float*)d_in[9];
    const float* U_r_b      = (const float*)d_in[10];
    const float* W_h_w      = (const float*)d_in[11];
    const float* W_h_b      = (const float*)d_in[12];
    const float* D1_w       = (const float*)d_in[13];
    const float* D1_b       = (const float*)d_in[14];
    const float* D2_w       = (const float*)d_in[15];
    const float* D2_b       = (const float*)d_in[16];
    const float* D3_w       = (const float*)d_in[17];
    const float* D3_b       = (const float*)d_in[18];
    const int*   depthp     = (n_in > 19) ? (const int*)d_in[19] : nullptr;
    float*       out        = (float*)d_out;

    float *fe, *x, *xzrh, *h, *hZU, *sumh, *z, *sumgh;
    float *Wpre, *bpre, *Wstep, *rv, *d1, *d2;
    cudaGetSymbolAddress((void**)&fe,    g_fe);
    cudaGetSymbolAddress((void**)&x,     g_x);
    cudaGetSymbolAddress((void**)&xzrh,  g_xzrh);
    cudaGetSymbolAddress((void**)&h,     g_h);
    cudaGetSymbolAddress((void**)&hZU,   g_hZU);
    cudaGetSymbolAddress((void**)&sumh,  g_sumh);
    cudaGetSymbolAddress((void**)&z,     g_z);
    cudaGetSymbolAddress((void**)&sumgh, g_sumgh);
    cudaGetSymbolAddress((void**)&Wpre,  g_Wpre);
    cudaGetSymbolAddress((void**)&bpre,  g_bpre);
    cudaGetSymbolAddress((void**)&Wstep, g_Wstep);
    cudaGetSymbolAddress((void**)&rv,    g_rv);
    cudaGetSymbolAddress((void**)&d1,    g_d1);
    cudaGetSymbolAddress((void**)&d2,    g_d2);

    const int TPB = 256;
    const int MH  = NMESS * HH;

    // h = 0 (for depth == 0 path; step0 overwrites when depth >= 1)
    zero_kernel<<<(MH + TPB - 1) / TPB, TPB>>>(h, MH);

    // pack fused weight matrices
    {
        int n = 3 * HH * HH + 2 * HH * HH;
        pack_kernel<<<(n + TPB - 1) / TPB, TPB>>>(W_z_w, W_h_w, W_r_w, U_r_w,
                                                  W_z_b, W_h_b, U_r_b,
                                                  Wpre, bpre, Wstep);
    }

    // embeddings + per-message features
    gather_rows_kernel<<<(NNODES * HH + TPB - 1) / TPB, TPB>>>(emb, fnode, fe, NNODES);
    gather_rows_kernel<<<(MH + TPB - 1) / TPB, TPB>>>(fe, fmess, x, NMESS);

    // xz | xh | xr = x @ Wpre^T + bpre  (one N=1350 GEMM)
    gemm_kernel<<<gemm_grid(NMESS, 3 * HH), 256>>>(x, HH, Wpre, HH,
        NMESS, 3 * HH, HH, 0, bpre, nullptr, 0, nullptr, nullptr,
        xzrh, 3 * HH, nullptr, 0);

    // step 0 specialized
    step0_kernel<<<(MH + TPB - 1) / TPB, TPB>>>(xzrh, h, depthp);

    // steps 1..14
    for (int s = 1; s < MAXDEPTH; s++) {
        // hZU = h @ [Wz_h ; U_r]^T   (N=900)
        gemm_kernel<<<gemm_grid(NMESS, 2 * HH), 256>>>(h, HH, Wstep, HH,
            NMESS, 2 * HH, HH, 2, nullptr, nullptr, 0, nullptr, nullptr,
            hZU, 2 * HH, depthp, s);
        // sum_h, z, sum_gh in one fused gather
        step_gather_kernel<<<(MH + TPB - 1) / TPB, TPB>>>(h, hZU, xzrh, mess_graph,
                                                          sumh, z, sumgh, depthp, s);
        // h = (1-z)*sumh + z*tanh(sumgh @ Wh_h^T + xh), masked
        gemm_kernel<<<gemm_grid(NMESS, HH), 256>>>(sumgh, HH, W_h_w + HH, 2 * HH,
            NMESS, HH, HH, 3, nullptr, xzrh + HH, 3 * HH, z, sumh,
            h, HH, depthp, s);
    }

    // readout + discriminator
    readout_kernel<<<(BB * HH + TPB - 1) / TPB, TPB>>>(fe, h, root_idx, node_graph, rv);
    gemm_kernel<<<gemm_grid(BB, DHH), 256>>>(rv, 2 * HH, D1_w, 2 * HH,
        BB, DHH, 2 * HH, 4, D1_b, nullptr, 0, nullptr, nullptr,
        d1, DHH, nullptr, 0);
    gemm_kernel<<<gemm_grid(BB, DHH), 256>>>(d1, DHH, D2_w, DHH,
        BB, DHH, DHH, 4, D2_b, nullptr, 0, nullptr, nullptr,
        d2, DHH, nullptr, 0);
    score_kernel<<<(BB * 32 + TPB - 1) / TPB, TPB>>>(d2, D3_w, D3_b, out);
}